// round 12
// baseline (speedup 1.0000x reference)
#include <cuda_runtime.h>

typedef unsigned long long ULL;

// Problem constants (fixed by the dataset)
#define BATCH   256
#define PASTN   512
#define HID     512
#define FUT     64
#define TOTT    576          // PASTN + FUT
#define KK      256          // HID/2 (k-pairs)

// Launch config
#define NCTA    128          // 4 batch-tiles x 32 unit-tiles
#define NTHR    512          // 16 warps
#define BTILE   64           // batches per CTA
#define UTILE   16           // hidden units per CTA (=> 64 gate rows)
#define GRPC    32           // CTAs per barrier group (one batch-tile)

// h staging chunks
#define CH      64           // k-pairs per chunk
#define NCHUNK  (KK / CH)    // 4

// ---------------- device globals (scratch; no allocation allowed) -----------
// h double buffer, packed k-pairs: [p][kk][b] as one ULL = (h[b][2kk], h[b][2kk+1])
__device__ ULL g_hbuf[2 * KK * BATCH];
__device__ float g_xT[PASTN * BATCH];                 // transposed input [t][b]
// 4 independent barrier groups (one per batch tile), 128B-strided counters
__device__ __align__(128) unsigned g_arrive[4 * 32];  // zero-init; returns to 0
__device__ __align__(128) unsigned g_release[4 * 32]; // monotone epochs

// ---------------- helpers ---------------------------------------------------
__device__ __forceinline__ void fma2(ULL &d, ULL a, ULL b) {
    // packed dual-fp32 FMA (Blackwell FFMA2) - only reachable via PTX
    asm("fma.rn.f32x2 %0, %1, %2, %0;" : "+l"(d) : "l"(a), "l"(b));
}
__device__ __forceinline__ float lo2(ULL v) { return __uint_as_float((unsigned)(v & 0xffffffffu)); }
__device__ __forceinline__ float hi2(ULL v) { return __uint_as_float((unsigned)(v >> 32)); }
__device__ __forceinline__ float sigf(float x) { return 1.0f / (1.0f + __expf(-x)); }

// Group-wide barrier over GRPC co-resident CTAs. The gpu-scope __threadfence()
// orders the h stores / REDs and (sm_103a) invalidates L1D (CCTL.IVALL) so
// post-barrier h loads are fresh.
__device__ __forceinline__ void group_barrier(int grp, unsigned target) {
    __syncthreads();
    if (threadIdx.x == 0) {
        __threadfence();
        unsigned prev = atomicAdd(&g_arrive[grp], 1u);
        if (prev == GRPC - 1) {
            g_arrive[grp] = 0;
            __threadfence();
            *((volatile unsigned *)&g_release[grp]) = target;
        } else {
            while ((int)(*((volatile unsigned *)&g_release[grp]) - target) < 0) { }
        }
        __threadfence();   // both paths: flush/invalidate L1D before reading new h
    }
    __syncthreads();
}

// ---------------- kernel ----------------------------------------------------
// dynamic smem: [0, 131072)B  = W_hh slice, layout [kk][gatepair][unit] 16B units
//               [131072, +65536)B = h chunk double buffer (2 x 32 KB)
extern __shared__ ULL wsm[];

__global__ void __launch_bounds__(NTHR, 1)
lstm_persist_kernel(const float *__restrict__ xin,    // [256][512][1]
                    const float *__restrict__ Wih,    // [2048][1]
                    const float *__restrict__ Whh,    // [2048][512]
                    const float *__restrict__ bih,    // [2048]
                    const float *__restrict__ bhh,    // [2048]
                    const float *__restrict__ Wdec,   // [1][512]
                    const float *__restrict__ bdec,   // [1]
                    float *__restrict__ out)          // [256][576][1]
{
    __shared__ float bsum_s[UTILE][4];
    __shared__ float wih_s[UTILE][4];
    __shared__ float part_s[UTILE][BTILE];  // decode partials [unit][batch]
    __shared__ unsigned ep_s;

    const int tid  = threadIdx.x;
    const int bt   = blockIdx.x & 3;           // batch tile 0..3
    const int jt   = blockIdx.x >> 2;          // unit tile 0..31
    const int w    = tid >> 5;                 // warp 0..15
    const int l    = tid & 31;
    const int rg   = w & 1;                    // row group (8 units each)
    const int wb   = w >> 1;                   // batch group 0..7 (8 batches each)
    const int rr   = l & 7;                    // unit within row group
    const int bb   = l >> 3;                   // batch pair within group (0..3)
    const int u_local = rg * 8 + rr;           // 0..15
    const int u_glob  = jt * UTILE + u_local;
    const int b0l  = wb * 8 + bb * 2;          // first of 2 owned batches (local)
    const int bg0  = bt * BTILE + b0l;         // global
    const int grp  = bt * 32;                  // barrier-group slot (128B strided)

    float *wsm_f = (float *)wsm;               // weight smem, float view
    ULL   *s_h   = wsm + UTILE * KK * 4;       // h chunk double buffer (after 128KB)

    // ---- prologue: stage W_hh slice, layout [kk][gp][u][ge][k&1] ----------
    // float index: kk*128 + (g>>1)*64 + uu*4 + (g&1)*2 + (k&1)
    for (int idx = tid; idx < UTILE * 4 * HID; idx += NTHR) {
        int k  = idx & (HID - 1);
        int g  = (idx >> 9) & 3;
        int uu = idx >> 11;
        int n  = jt * UTILE + uu;
        float v = Whh[(g * HID + n) * HID + k];
        wsm_f[(k >> 1) * 128 + (g >> 1) * 64 + uu * 4 + (g & 1) * 2 + (k & 1)] = v;
    }
    if (tid < UTILE * 4) {
        int uu = tid >> 2, g = tid & 3;
        int j  = g * HID + jt * UTILE + uu;
        bsum_s[uu][g] = bih[j] + bhh[j];
        wih_s[uu][g]  = Wih[j];              // FEAT = 1
    }
    const float bdec_v = bdec[0];
    const float wd = Wdec[u_glob];

    // transpose input: x[t][b] for coalesced per-step loads
    for (int i = blockIdx.x * NTHR + tid; i < PASTN * BATCH; i += NCTA * NTHR) {
        int t = i >> 8, b = i & (BATCH - 1);
        g_xT[i] = xin[b * PASTN + t];
    }
    // init output slice of this batch tile with b_dec (atomics accumulate onto it)
    for (int i = jt * NTHR + tid; i < BTILE * TOTT; i += 32 * NTHR) {
        int bl = i / TOTT, tt = i - bl * TOTT;
        out[(bt * BTILE + bl) * TOTT + tt] = bdec_v;
    }

    if (tid == 0) ep_s = *((volatile unsigned *)&g_release[grp]);  // replay-safe base

    // ---- init h0 = 0.01 into this thread's owned float slots --------------
    const int kk_h = u_glob >> 1;
    const int hsub = u_glob & 1;
    {
        float *ghf = (float *)g_hbuf;        // buffer p=0
        ghf[(kk_h * BATCH + bg0 + 0) * 2 + hsub] = 0.01f;
        ghf[(kk_h * BATCH + bg0 + 1) * 2 + hsub] = 0.01f;
    }
    float cst0 = 0.01f, cst1 = 0.01f;
    __syncthreads();

    unsigned epoch = ep_s;
    group_barrier(grp, ++epoch);             // h0, xT, out-init visible in group

    // staging indices: chunk = CH kk x 32 u2 = 2048 u2; thread stages
    // u2 elements tid + 512*q (q=0..3): kk_l = st_kk + 16q, pair = st_pr
    const int st_kk = tid >> 5;              // 0..15
    const int st_pr = tid & 31;

    int p = 0;

    for (int t = 0; t < TOTT; ++t) {
        // inputs for this thread's 2 batches
        float x0, x1;
        if (t < PASTN) {
            float2 xx = *(const float2 *)&g_xT[t * BATCH + bg0];
            x0 = xx.x; x1 = xx.y;
        } else {
            x0 = out[(bg0 + 0) * TOTT + (t - 1)];
            x1 = out[(bg0 + 1) * TOTT + (t - 1)];
        }

        const ulonglong2 *__restrict__ hp2 =
            (const ulonglong2 *)(g_hbuf + p * (KK * BATCH)) + bt * 32;

        // accumulators: 2 batches x 4 gates, k-pair packed
        ULL a00 = 0, a01 = 0, a02 = 0, a03 = 0;
        ULL a10 = 0, a11 = 0, a12 = 0, a13 = 0;

        // preload chunk 0 into buffer 0 (4 LDG.128 in flight per thread)
        {
            ulonglong2 tmp[4];
#pragma unroll
            for (int q = 0; q < 4; ++q)
                tmp[q] = hp2[(st_kk + 16 * q) * 128 + st_pr];
            ulonglong2 *dst = (ulonglong2 *)s_h;
#pragma unroll
            for (int q = 0; q < 4; ++q)
                dst[tid + 512 * q] = tmp[q];
        }
        __syncthreads();

        for (int c = 0; c < NCHUNK; ++c) {
            // front-batched loads for chunk c+1 (covered by consume body)
            ulonglong2 tmp[4];
            if (c + 1 < NCHUNK) {
                const ulonglong2 *src = hp2 + (c + 1) * (CH * 128);
#pragma unroll
                for (int q = 0; q < 4; ++q)
                    tmp[q] = src[(st_kk + 16 * q) * 128 + st_pr];
            }

            const ULL *__restrict__ sc = s_h + (c & 1) * (CH * 64) + b0l;
            const float *__restrict__ wf = wsm_f + (c * CH) * 128 + u_local * 4;
#pragma unroll 16
            for (int kk = 0; kk < CH; ++kk) {
                // weights: (i,f) and (g,o) k-pairs, conflict-free, bcast x4
                ulonglong2 wp0 = *(const ulonglong2 *)(wf + kk * 128);
                ulonglong2 wp1 = *(const ulonglong2 *)(wf + kk * 128 + 64);
                // h: 2 owned batches' k-pairs in one LDS.128, bcast x8
                ulonglong2 h01 = *(const ulonglong2 *)(sc + kk * 64);
                fma2(a00, h01.x, wp0.x); fma2(a01, h01.x, wp0.y);
                fma2(a02, h01.x, wp1.x); fma2(a03, h01.x, wp1.y);
                fma2(a10, h01.y, wp0.x); fma2(a11, h01.y, wp0.y);
                fma2(a12, h01.y, wp1.x); fma2(a13, h01.y, wp1.y);
            }

            if (c + 1 < NCHUNK) {
                ulonglong2 *dst = (ulonglong2 *)(s_h + ((c + 1) & 1) * (CH * 64));
#pragma unroll
                for (int q = 0; q < 4; ++q)
                    dst[tid + 512 * q] = tmp[q];
            }
            __syncthreads();
        }

        // ---- LSTM cell update (gates ordered i,f,g,o), 2 batches ----------
        const int p1 = p ^ 1;
        float *ghn = (float *)(g_hbuf + p1 * (KK * BATCH));
        const float wi0 = wih_s[u_local][0], wi1 = wih_s[u_local][1];
        const float wi2 = wih_s[u_local][2], wi3 = wih_s[u_local][3];
        const float bs0 = bsum_s[u_local][0], bs1 = bsum_s[u_local][1];
        const float bs2 = bsum_s[u_local][2], bs3 = bsum_s[u_local][3];
        float hv0, hv1;
        {
            float gi = lo2(a00) + hi2(a00) + x0 * wi0 + bs0;
            float gf = lo2(a01) + hi2(a01) + x0 * wi1 + bs1;
            float gg = lo2(a02) + hi2(a02) + x0 * wi2 + bs2;
            float go = lo2(a03) + hi2(a03) + x0 * wi3 + bs3;
            cst0 = sigf(gf) * cst0 + sigf(gi) * tanhf(gg);
            hv0  = sigf(go) * tanhf(cst0);
        }
        {
            float gi = lo2(a10) + hi2(a10) + x1 * wi0 + bs0;
            float gf = lo2(a11) + hi2(a11) + x1 * wi1 + bs1;
            float gg = lo2(a12) + hi2(a12) + x1 * wi2 + bs2;
            float go = lo2(a13) + hi2(a13) + x1 * wi3 + bs3;
            cst1 = sigf(gf) * cst1 + sigf(gi) * tanhf(gg);
            hv1  = sigf(go) * tanhf(cst1);
        }

        ghn[(kk_h * BATCH + bg0 + 0) * 2 + hsub] = hv0;
        ghn[(kk_h * BATCH + bg0 + 1) * 2 + hsub] = hv1;

        // ---- decode contribution from registers (no h re-read) ------------
        *(float2 *)&part_s[u_local][b0l] = make_float2(hv0 * wd, hv1 * wd);
        __syncthreads();
        if (tid < 64) {
            float s = part_s[0][tid];
#pragma unroll
            for (int q = 1; q < UTILE; ++q) s += part_s[q][tid];
            atomicAdd(&out[(bt * BTILE + tid) * TOTT + t], s);   // REDG, no return
        }

        group_barrier(grp, ++epoch);         // h + y complete, L1 invalidated
        p = p1;
    }
}

// ---------------- launch -----------------------------------------------------
extern "C" void kernel_launch(void *const *d_in, const int *in_sizes, int n_in,
                              void *d_out, int out_size) {
    const float *xin  = (const float *)d_in[0];   // input_seq [256,512,1]
    // d_in[1] = future_n (fixed 64, hardcoded)
    const float *Wih  = (const float *)d_in[2];   // [2048,1]
    const float *Whh  = (const float *)d_in[3];   // [2048,512]
    const float *bih  = (const float *)d_in[4];   // [2048]
    const float *bhh  = (const float *)d_in[5];   // [2048]
    const float *Wdec = (const float *)d_in[6];   // [1,512]
    const float *bdec = (const float *)d_in[7];   // [1]
    float *out = (float *)d_out;                  // [256,576,1]

    // 128 KB weights + 64 KB h chunk double buffer = 192 KB
    const int SMEM = UTILE * 4 * HID * 4 + 2 * CH * BTILE * 8;
    static_assert(UTILE * 4 * HID * 4 == 131072, "smem size");
    cudaFuncSetAttribute(lstm_persist_kernel,
                         cudaFuncAttributeMaxDynamicSharedMemorySize, SMEM);

    lstm_persist_kernel<<<NCTA, NTHR, SMEM>>>(xin, Wih, Whh, bih, bhh,
                                              Wdec, bdec, out);
    (void)in_sizes; (void)n_in; (void)out_size;
}

// round 13
// speedup vs baseline: 1.3578x; 1.3578x over previous
#include <cuda_runtime.h>

typedef unsigned long long ULL;

// Problem constants (fixed by the dataset)
#define BATCH   256
#define PASTN   512
#define HID     512
#define FUT     64
#define TOTT    576          // PASTN + FUT
#define KK      256          // HID/2 (k-pairs)

// Launch config
#define NCTA    128          // 4 batch-tiles x 32 unit-tiles
#define NTHR    256          // 8 warps: best measured tile (R11)
#define BTILE   64           // batches per CTA
#define UTILE   16           // hidden units per CTA (=> 64 gate rows)
#define GRPC    32           // CTAs per barrier group (one batch-tile)

// h staging chunks
#define CH      64           // k-pairs per chunk
#define NCHUNK  (KK / CH)    // 4

// ---------------- device globals (scratch; no allocation allowed) -----------
// h double buffer, packed k-pairs: [p][kk][b] as one ULL = (h[b][2kk], h[b][2kk+1])
__device__ ULL g_hbuf[2 * KK * BATCH];
__device__ float g_xT[PASTN * BATCH];                 // transposed input [t][b]
// 4 independent barrier groups (one per batch tile), 128B-strided counters
__device__ __align__(128) unsigned g_arrive[4 * 32];  // zero-init; returns to 0
__device__ __align__(128) unsigned g_release[4 * 32]; // monotone epochs

// ---------------- helpers ---------------------------------------------------
__device__ __forceinline__ void fma2(ULL &d, ULL a, ULL b) {
    // packed dual-fp32 FMA (Blackwell FFMA2) - only reachable via PTX
    asm("fma.rn.f32x2 %0, %1, %2, %0;" : "+l"(d) : "l"(a), "l"(b));
}
__device__ __forceinline__ float lo2(ULL v) { return __uint_as_float((unsigned)(v & 0xffffffffu)); }
__device__ __forceinline__ float hi2(ULL v) { return __uint_as_float((unsigned)(v >> 32)); }
__device__ __forceinline__ float sigf(float x) { return 1.0f / (1.0f + __expf(-x)); }

// barrier core executed by ONE thread: fence, arrive, (release|poll), fence.
// The gpu-scope __threadfence() orders global stores and (sm_103a) invalidates
// L1D (CCTL.IVALL) so post-barrier staged h LDGs are fresh.
__device__ __forceinline__ void barrier_core(int grp, unsigned target) {
    __threadfence();
    unsigned prev = atomicAdd(&g_arrive[grp], 1u);
    if (prev == GRPC - 1) {
        g_arrive[grp] = 0;
        __threadfence();
        *((volatile unsigned *)&g_release[grp]) = target;
    } else {
        while ((int)(*((volatile unsigned *)&g_release[grp]) - target) < 0) { }
    }
    __threadfence();
}

__device__ __forceinline__ void group_barrier(int grp, unsigned target) {
    __syncthreads();
    if (threadIdx.x == 0) barrier_core(grp, target);
    __syncthreads();
}

// ---------------- kernel ----------------------------------------------------
// dynamic smem: [0, 131072)B  = W_hh slice, layout [kk][gatepair][unit] 16B units
//               [131072, +65536)B = h chunk double buffer (2 x 32 KB)
extern __shared__ ULL wsm[];

__global__ void __launch_bounds__(NTHR, 1)
lstm_persist_kernel(const float *__restrict__ xin,    // [256][512][1]
                    const float *__restrict__ Wih,    // [2048][1]
                    const float *__restrict__ Whh,    // [2048][512]
                    const float *__restrict__ bih,    // [2048]
                    const float *__restrict__ bhh,    // [2048]
                    const float *__restrict__ Wdec,   // [1][512]
                    const float *__restrict__ bdec,   // [1]
                    float *__restrict__ out)          // [256][576][1]
{
    __shared__ float bsum_s[UTILE][4];
    __shared__ float wih_s[UTILE][4];
    __shared__ float part_s[UTILE][BTILE];  // decode partials [unit][batch]
    __shared__ unsigned ep_s;

    const int tid  = threadIdx.x;
    const int bt   = blockIdx.x & 3;           // batch tile 0..3
    const int jt   = blockIdx.x >> 2;          // unit tile 0..31
    const int w    = tid >> 5;                 // warp 0..7
    const int l    = tid & 31;
    const int rg   = w & 1;                    // row group (8 units each)
    const int wb   = w >> 1;                   // batch group (16 batches each)
    const int rr   = l & 7;                    // unit within row group
    const int bb   = l >> 3;                   // batch quad within batch group
    const int u_local = rg * 8 + rr;           // 0..15
    const int u_glob  = jt * UTILE + u_local;
    const int b0l  = wb * 16 + bb * 4;         // first of 4 owned batches (local)
    const int bg0  = bt * BTILE + b0l;         // global
    const int grp  = bt * 32;                  // barrier-group slot (128B strided)

    float *wsm_f = (float *)wsm;               // weight smem, float view
    ULL   *s_h   = wsm + UTILE * KK * 4;       // h chunk double buffer (after 128KB)

    // ---- prologue: stage W_hh slice, layout [kk][gp][u][ge][k&1] ----------
    // float index: kk*128 + (g>>1)*64 + uu*4 + (g&1)*2 + (k&1)
    for (int idx = tid; idx < UTILE * 4 * HID; idx += NTHR) {
        int k  = idx & (HID - 1);
        int g  = (idx >> 9) & 3;
        int uu = idx >> 11;
        int n  = jt * UTILE + uu;
        float v = Whh[(g * HID + n) * HID + k];
        wsm_f[(k >> 1) * 128 + (g >> 1) * 64 + uu * 4 + (g & 1) * 2 + (k & 1)] = v;
    }
    if (tid < UTILE * 4) {
        int uu = tid >> 2, g = tid & 3;
        int j  = g * HID + jt * UTILE + uu;
        bsum_s[uu][g] = bih[j] + bhh[j];
        wih_s[uu][g]  = Wih[j];              // FEAT = 1
    }
    const float bdec_v = bdec[0];
    const float wd = Wdec[u_glob];

    // transpose input: x[t][b] for coalesced per-step loads
    for (int i = blockIdx.x * NTHR + tid; i < PASTN * BATCH; i += NCTA * NTHR) {
        int t = i >> 8, b = i & (BATCH - 1);
        g_xT[i] = xin[b * PASTN + t];
    }
    // init output slice of this batch tile with b_dec (atomics accumulate onto it)
    for (int i = jt * NTHR + tid; i < BTILE * TOTT; i += 32 * NTHR) {
        int bl = i / TOTT, tt = i - bl * TOTT;
        out[(bt * BTILE + bl) * TOTT + tt] = bdec_v;
    }

    if (tid == 0) ep_s = *((volatile unsigned *)&g_release[grp]);  // replay-safe base

    // ---- init h0 = 0.01 into this thread's owned float slots --------------
    const int kk_h = u_glob >> 1;
    const int hsub = u_glob & 1;
    {
        float *ghf = (float *)g_hbuf;        // buffer p=0
#pragma unroll
        for (int j = 0; j < 4; ++j)
            ghf[(kk_h * BATCH + bg0 + j) * 2 + hsub] = 0.01f;
    }
    float cst0 = 0.01f, cst1 = 0.01f, cst2 = 0.01f, cst3 = 0.01f;
    __syncthreads();

    unsigned epoch = ep_s;
    group_barrier(grp, ++epoch);             // h0, xT, out-init visible in group

    // hoist invariant per-unit constants out of the t loop
    const float wi0 = wih_s[u_local][0], wi1 = wih_s[u_local][1];
    const float wi2 = wih_s[u_local][2], wi3 = wih_s[u_local][3];
    const float bs0 = bsum_s[u_local][0], bs1 = bsum_s[u_local][1];
    const float bs2 = bsum_s[u_local][2], bs3 = bsum_s[u_local][3];

    // staging indices: chunk = CH kk x 32 u2 = 2048 u2; thread stages
    // u2 elements tid + 256*q (q=0..7): kk_l = st_kk + 8q, pair = st_pr
    const int st_kk = tid >> 5;              // 0..7
    const int st_pr = tid & 31;

    int p = 0;

    for (int t = 0; t < TOTT; ++t) {
        // inputs for this thread's 4 batches
        float x0, x1, x2, x3;
        if (t < PASTN) {
            float4 xx = *(const float4 *)&g_xT[t * BATCH + bg0];
            x0 = xx.x; x1 = xx.y; x2 = xx.z; x3 = xx.w;
        } else {
            x0 = out[(bg0 + 0) * TOTT + (t - 1)];
            x1 = out[(bg0 + 1) * TOTT + (t - 1)];
            x2 = out[(bg0 + 2) * TOTT + (t - 1)];
            x3 = out[(bg0 + 3) * TOTT + (t - 1)];
        }

        const ulonglong2 *__restrict__ hp2 =
            (const ulonglong2 *)(g_hbuf + p * (KK * BATCH)) + bt * 32;

        // accumulators: 4 batches x 4 gates, k-pair packed
        ULL a00 = 0, a01 = 0, a02 = 0, a03 = 0;
        ULL a10 = 0, a11 = 0, a12 = 0, a13 = 0;
        ULL a20 = 0, a21 = 0, a22 = 0, a23 = 0;
        ULL a30 = 0, a31 = 0, a32 = 0, a33 = 0;

        // preload chunk 0 into buffer 0 (8 LDG.128 in flight per thread)
        {
            ulonglong2 tmp[8];
#pragma unroll
            for (int q = 0; q < 8; ++q)
                tmp[q] = hp2[(st_kk + 8 * q) * 128 + st_pr];
            ulonglong2 *dst = (ulonglong2 *)s_h;
#pragma unroll
            for (int q = 0; q < 8; ++q)
                dst[tid + 256 * q] = tmp[q];
        }
        __syncthreads();

        for (int c = 0; c < NCHUNK; ++c) {
            // front-batched loads for chunk c+1 (covered by consume body)
            ulonglong2 tmp[8];
            if (c + 1 < NCHUNK) {
                const ulonglong2 *src = hp2 + (c + 1) * (CH * 128);
#pragma unroll
                for (int q = 0; q < 8; ++q)
                    tmp[q] = src[(st_kk + 8 * q) * 128 + st_pr];
            }

            const ULL *__restrict__ sc = s_h + (c & 1) * (CH * 64) + b0l;
            const float *__restrict__ wf = wsm_f + (c * CH) * 128 + u_local * 4;
#pragma unroll 16
            for (int kk = 0; kk < CH; ++kk) {
                // weights: (i,f) and (g,o) k-pairs, conflict-free, bb-broadcast
                ulonglong2 wp0 = *(const ulonglong2 *)(wf + kk * 128);
                ulonglong2 wp1 = *(const ulonglong2 *)(wf + kk * 128 + 64);
                // h: 4 owned batches' k-pairs, conflict-free, rr-broadcast
                ulonglong2 h01 = *(const ulonglong2 *)(sc + kk * 64);
                ulonglong2 h23 = *(const ulonglong2 *)(sc + kk * 64 + 2);
                fma2(a00, h01.x, wp0.x); fma2(a01, h01.x, wp0.y);
                fma2(a02, h01.x, wp1.x); fma2(a03, h01.x, wp1.y);
                fma2(a10, h01.y, wp0.x); fma2(a11, h01.y, wp0.y);
                fma2(a12, h01.y, wp1.x); fma2(a13, h01.y, wp1.y);
                fma2(a20, h23.x, wp0.x); fma2(a21, h23.x, wp0.y);
                fma2(a22, h23.x, wp1.x); fma2(a23, h23.x, wp1.y);
                fma2(a30, h23.y, wp0.x); fma2(a31, h23.y, wp0.y);
                fma2(a32, h23.y, wp1.x); fma2(a33, h23.y, wp1.y);
            }

            if (c + 1 < NCHUNK) {
                ulonglong2 *dst = (ulonglong2 *)(s_h + ((c + 1) & 1) * (CH * 64));
#pragma unroll
                for (int q = 0; q < 8; ++q)
                    dst[tid + 256 * q] = tmp[q];
            }
            __syncthreads();
        }

        // ---- LSTM cell update (gates ordered i,f,g,o), 4 batches ----------
        const int p1 = p ^ 1;
        float *ghn = (float *)(g_hbuf + p1 * (KK * BATCH));
        float hv0, hv1, hv2, hv3;
        {
            float gi = lo2(a00) + hi2(a00) + x0 * wi0 + bs0;
            float gf = lo2(a01) + hi2(a01) + x0 * wi1 + bs1;
            float gg = lo2(a02) + hi2(a02) + x0 * wi2 + bs2;
            float go = lo2(a03) + hi2(a03) + x0 * wi3 + bs3;
            cst0 = sigf(gf) * cst0 + sigf(gi) * tanhf(gg);
            hv0  = sigf(go) * tanhf(cst0);
        }
        {
            float gi = lo2(a10) + hi2(a10) + x1 * wi0 + bs0;
            float gf = lo2(a11) + hi2(a11) + x1 * wi1 + bs1;
            float gg = lo2(a12) + hi2(a12) + x1 * wi2 + bs2;
            float go = lo2(a13) + hi2(a13) + x1 * wi3 + bs3;
            cst1 = sigf(gf) * cst1 + sigf(gi) * tanhf(gg);
            hv1  = sigf(go) * tanhf(cst1);
        }
        {
            float gi = lo2(a20) + hi2(a20) + x2 * wi0 + bs0;
            float gf = lo2(a21) + hi2(a21) + x2 * wi1 + bs1;
            float gg = lo2(a22) + hi2(a22) + x2 * wi2 + bs2;
            float go = lo2(a23) + hi2(a23) + x2 * wi3 + bs3;
            cst2 = sigf(gf) * cst2 + sigf(gi) * tanhf(gg);
            hv2  = sigf(go) * tanhf(cst2);
        }
        {
            float gi = lo2(a30) + hi2(a30) + x3 * wi0 + bs0;
            float gf = lo2(a31) + hi2(a31) + x3 * wi1 + bs1;
            float gg = lo2(a32) + hi2(a32) + x3 * wi2 + bs2;
            float go = lo2(a33) + hi2(a33) + x3 * wi3 + bs3;
            cst3 = sigf(gf) * cst3 + sigf(gi) * tanhf(gg);
            hv3  = sigf(go) * tanhf(cst3);
        }

        ghn[(kk_h * BATCH + bg0 + 0) * 2 + hsub] = hv0;
        ghn[(kk_h * BATCH + bg0 + 1) * 2 + hsub] = hv1;
        ghn[(kk_h * BATCH + bg0 + 2) * 2 + hsub] = hv2;
        ghn[(kk_h * BATCH + bg0 + 3) * 2 + hsub] = hv3;

        // decode partials from registers (no h re-read)
        *(float4 *)&part_s[u_local][b0l] =
            make_float4(hv0 * wd, hv1 * wd, hv2 * wd, hv3 * wd);

        ++epoch;
        __syncthreads();     // part_s ready; all h stores issued CTA-wide

        if (t < PASTN - 1) {
            // past phase: nothing reads out[t] next step -> overlap the
            // inter-CTA barrier (last thread) with decode reduce + REDG.
            if (tid == NTHR - 1) barrier_core(grp, epoch);
            if (tid < 64) {
                float s = part_s[0][tid];
#pragma unroll
                for (int q = 1; q < UTILE; ++q) s += part_s[q][tid];
                atomicAdd(&out[(bt * BTILE + tid) * TOTT + t], s);  // REDG
            }
            __syncthreads(); // waits for barrier_core completion too
        } else {
            // future phase (and t==PASTN-1): out[t] feeds x[t+1] in other
            // CTAs -> REDG must complete before the barrier releases.
            if (tid < 64) {
                float s = part_s[0][tid];
#pragma unroll
                for (int q = 1; q < UTILE; ++q) s += part_s[q][tid];
                atomicAdd(&out[(bt * BTILE + tid) * TOTT + t], s);
            }
            __syncthreads();
            if (tid == 0) barrier_core(grp, epoch);
            __syncthreads();
        }
        p = p1;
    }
}

// ---------------- launch -----------------------------------------------------
extern "C" void kernel_launch(void *const *d_in, const int *in_sizes, int n_in,
                              void *d_out, int out_size) {
    const float *xin  = (const float *)d_in[0];   // input_seq [256,512,1]
    // d_in[1] = future_n (fixed 64, hardcoded)
    const float *Wih  = (const float *)d_in[2];   // [2048,1]
    const float *Whh  = (const float *)d_in[3];   // [2048,512]
    const float *bih  = (const float *)d_in[4];   // [2048]
    const float *bhh  = (const float *)d_in[5];   // [2048]
    const float *Wdec = (const float *)d_in[6];   // [1,512]
    const float *bdec = (const float *)d_in[7];   // [1]
    float *out = (float *)d_out;                  // [256,576,1]

    // 128 KB weights + 64 KB h chunk double buffer = 192 KB
    const int SMEM = UTILE * 4 * HID * 4 + 2 * CH * BTILE * 8;
    static_assert(UTILE * 4 * HID * 4 == 131072, "smem size");
    cudaFuncSetAttribute(lstm_persist_kernel,
                         cudaFuncAttributeMaxDynamicSharedMemorySize, SMEM);

    lstm_persist_kernel<<<NCTA, NTHR, SMEM>>>(xin, Wih, Whh, bih, bhh,
                                              Wdec, bdec, out);
    (void)in_sizes; (void)n_in; (void)out_size;
}

// round 15
// speedup vs baseline: 1.3939x; 1.0265x over previous
#include <cuda_runtime.h>

typedef unsigned long long ULL;

// Problem constants (fixed by the dataset)
#define BATCH   256
#define PASTN   512
#define HID     512
#define FUT     64
#define TOTT    576          // PASTN + FUT
#define KK      256          // HID/2 (k-pairs)

// Launch config: 128 CTAs = 2 bt-pairs x 64 unit-tiles; each CTA runs TWO
// independent sequences (bt-pair) in two 128-thread halves.
#define NCTA    128
#define NTHR    256          // 8 warps: warps 0-3 = half 0, warps 4-7 = half 1
#define BTILE   64           // batches per sequence
#define UTILE   8            // hidden units per CTA (shared weights)
#define GRPC    64           // CTAs per inter-CTA barrier group (one bt)

// h staging chunks (per half)
#define CH      32           // k-pairs per chunk
#define NCHUNK  (KK / CH)    // 8

// ---------------- device globals (scratch; no allocation allowed) -----------
// h double buffer, packed k-pairs: [p][kk][b] as one ULL = (h[b][2kk], h[b][2kk+1])
__device__ ULL g_hbuf[2 * KK * BATCH];
__device__ float g_xT[PASTN * BATCH];                 // transposed input [t][b]
// 4 independent barrier groups (one per bt), 128B-strided counters
__device__ __align__(128) unsigned g_arrive[4 * 32];  // zero-init; returns to 0
__device__ __align__(128) unsigned g_release[4 * 32]; // monotone epochs
__device__ unsigned g_garrive;                        // global init barrier
__device__ unsigned g_grelease;                       // monotone

// ---------------- helpers ---------------------------------------------------
__device__ __forceinline__ void fma2(ULL &d, ULL a, ULL b) {
    // packed dual-fp32 FMA (Blackwell FFMA2) - only reachable via PTX
    asm("fma.rn.f32x2 %0, %1, %2, %0;" : "+l"(d) : "l"(a), "l"(b));
}
__device__ __forceinline__ float lo2(ULL v) { return __uint_as_float((unsigned)(v & 0xffffffffu)); }
__device__ __forceinline__ float hi2(ULL v) { return __uint_as_float((unsigned)(v >> 32)); }
__device__ __forceinline__ float sigf(float x) { return 1.0f / (1.0f + __expf(-x)); }

#define NBAR(id) asm volatile("bar.sync %0, %1;" :: "r"(id), "r"(128) : "memory")

// inter-CTA barrier core executed by ONE thread of a half. gpu-scope fences
// order global stores and (sm_103a) invalidate L1D (CCTL.IVALL).
__device__ __forceinline__ void barrier_core(int grp, unsigned target) {
    __threadfence();
    unsigned prev = atomicAdd(&g_arrive[grp], 1u);
    if (prev == GRPC - 1) {
        g_arrive[grp] = 0;
        __threadfence();
        *((volatile unsigned *)&g_release[grp]) = target;
    } else {
        while ((int)(*((volatile unsigned *)&g_release[grp]) - target) < 0) { }
    }
    __threadfence();
}

__device__ __forceinline__ void global_barrier_core(unsigned target) {
    __threadfence();
    unsigned prev = atomicAdd(&g_garrive, 1u);
    if (prev == NCTA - 1) {
        g_garrive = 0;
        __threadfence();
        *((volatile unsigned *)&g_grelease) = target;
    } else {
        while ((int)(*((volatile unsigned *)&g_grelease) - target) < 0) { }
    }
    __threadfence();
}

// ---------------- kernel ----------------------------------------------------
// dynamic smem: [0, 8192) ULL       = W_hh slice for 8 units (64 KB, shared)
//               [8192, 16384) ULL   = h staging: half0 2x16KB, half1 2x16KB
extern __shared__ ULL wsm[];

__global__ void __launch_bounds__(NTHR, 1)
lstm_persist_kernel(const float *__restrict__ xin,    // [256][512][1]
                    const float *__restrict__ Wih,    // [2048][1]
                    const float *__restrict__ Whh,    // [2048][512]
                    const float *__restrict__ bih,    // [2048]
                    const float *__restrict__ bhh,    // [2048]
                    const float *__restrict__ Wdec,   // [1][512]
                    const float *__restrict__ bdec,   // [1]
                    float *__restrict__ out)          // [256][576][1]
{
    __shared__ float bsum_s[UTILE][4];
    __shared__ float wih_s[UTILE][4];
    __shared__ float part_s[2][UTILE][BTILE];  // decode partials per half
    __shared__ unsigned ep_sh[2];
    __shared__ unsigned gep_sh;

    const int tid    = threadIdx.x;
    const int btpair = blockIdx.x & 1;         // 0: bt{0,1}, 1: bt{2,3}
    const int jt     = blockIdx.x >> 1;        // unit tile 0..63
    const int half   = tid >> 7;               // 0 or 1 (4 warps each)
    const int ht     = tid & 127;              // thread id within half
    const int w_h    = ht >> 5;                // warp within half 0..3
    const int l      = ht & 31;
    const int u_local = l & 7;                 // unit 0..7
    const int bb     = l >> 3;                 // batch quad 0..3
    const int u_glob = jt * UTILE + u_local;
    const int b0l    = w_h * 16 + bb * 4;      // first of 4 owned batches (local)
    const int bt     = btpair * 2 + half;      // this half's sequence
    const int bg0    = bt * BTILE + b0l;       // global batch
    const int grp    = bt * 32;                // barrier-group slot (128B strided)
    const int NB_ID  = 1 + half;               // named barrier id per half

    float *wsm_f  = (float *)wsm;              // weight smem, float view
    ULL   *s_half = wsm + 8192 + half * 4096;  // this half's 2x16KB staging

    // ---- prologue (whole CTA) ---------------------------------------------
    // weights, layout float idx: kk*64 + (g>>1)*32 + uu*4 + (g&1)*2 + (k&1)
    for (int idx = tid; idx < UTILE * 4 * HID; idx += NTHR) {
        int k  = idx & (HID - 1);
        int g  = (idx >> 9) & 3;
        int uu = idx >> 11;                    // 0..7
        int n  = jt * UTILE + uu;
        float v = Whh[(g * HID + n) * HID + k];
        wsm_f[(k >> 1) * 64 + (g >> 1) * 32 + uu * 4 + (g & 1) * 2 + (k & 1)] = v;
    }
    if (tid < UTILE * 4) {
        int uu = tid >> 2, g = tid & 3;
        int j  = g * HID + jt * UTILE + uu;
        bsum_s[uu][g] = bih[j] + bhh[j];
        wih_s[uu][g]  = Wih[j];              // FEAT = 1
    }
    const float bdec_v = bdec[0];
    const float wd = Wdec[u_glob];

    // transpose input: x[t][b] (all 128 CTAs cooperate)
    for (int i = blockIdx.x * NTHR + tid; i < PASTN * BATCH; i += NCTA * NTHR) {
        int t = i >> 8, b = i & (BATCH - 1);
        g_xT[i] = xin[b * PASTN + t];
    }
    // out init with b_dec for both of this CTA's sequences (64 CTAs per bt)
    for (int s = 0; s < 2; ++s) {
        int btx = btpair * 2 + s;
        for (int i = jt * NTHR + tid; i < BTILE * TOTT; i += 64 * NTHR) {
            int bl = i / TOTT, tt = i - bl * TOTT;
            out[(btx * BTILE + bl) * TOTT + tt] = bdec_v;
        }
    }

    if (tid == 0) gep_sh = *((volatile unsigned *)&g_grelease);
    if (ht == 0)  ep_sh[half] = *((volatile unsigned *)&g_release[grp]);

    // h0 = 0.01 into this thread's owned float slots
    const int kk_h = u_glob >> 1;
    const int hsub = u_glob & 1;
    {
        float *ghf = (float *)g_hbuf;        // buffer p=0
#pragma unroll
        for (int j = 0; j < 4; ++j)
            ghf[(kk_h * BATCH + bg0 + j) * 2 + hsub] = 0.01f;
    }
    float cst0 = 0.01f, cst1 = 0.01f, cst2 = 0.01f, cst3 = 0.01f;
    __syncthreads();

    // one TRUE global barrier: h0 + g_xT + out-init visible to all CTAs
    if (tid == 0) global_barrier_core(gep_sh + 1);
    __syncthreads();

    // hoisted per-unit constants
    const float wi0 = wih_s[u_local][0], wi1 = wih_s[u_local][1];
    const float wi2 = wih_s[u_local][2], wi3 = wih_s[u_local][3];
    const float bs0 = bsum_s[u_local][0], bs1 = bsum_s[u_local][1];
    const float bs2 = bsum_s[u_local][2], bs3 = bsum_s[u_local][3];

    // staging indices: chunk = CH(32) kk x 32 u2 = 1024 u2; thread stages
    // u2 idx = ht + 128*q (q=0..7): kk_l = st_kk + 4q, pair = st_pr
    const int st_kk = ht >> 5;               // 0..3
    const int st_pr = ht & 31;

    unsigned epoch = ep_sh[half];
    int p = 0;

    for (int t = 0; t < TOTT; ++t) {
        // inputs for this thread's 4 batches
        float x0, x1, x2, x3;
        if (t < PASTN) {
            float4 xx = *(const float4 *)&g_xT[t * BATCH + bg0];
            x0 = xx.x; x1 = xx.y; x2 = xx.z; x3 = xx.w;
        } else {
            x0 = out[(bg0 + 0) * TOTT + (t - 1)];
            x1 = out[(bg0 + 1) * TOTT + (t - 1)];
            x2 = out[(bg0 + 2) * TOTT + (t - 1)];
            x3 = out[(bg0 + 3) * TOTT + (t - 1)];
        }

        const ulonglong2 *__restrict__ hp2 =
            (const ulonglong2 *)(g_hbuf + p * (KK * BATCH)) + bt * 32;

        // accumulators: 4 batches x 4 gates, k-pair packed
        ULL a00 = 0, a01 = 0, a02 = 0, a03 = 0;
        ULL a10 = 0, a11 = 0, a12 = 0, a13 = 0;
        ULL a20 = 0, a21 = 0, a22 = 0, a23 = 0;
        ULL a30 = 0, a31 = 0, a32 = 0, a33 = 0;

        // preload chunk 0 into buffer 0 (8 LDG.128 in flight per thread)
        {
            ulonglong2 tmp[8];
#pragma unroll
            for (int q = 0; q < 8; ++q)
                tmp[q] = hp2[(st_kk + 4 * q) * 128 + st_pr];
            ulonglong2 *dst = (ulonglong2 *)s_half;
#pragma unroll
            for (int q = 0; q < 8; ++q)
                dst[ht + 128 * q] = tmp[q];
        }
        NBAR(NB_ID);

        for (int c = 0; c < NCHUNK; ++c) {
            // front-batched loads for chunk c+1 (covered by consume body)
            ulonglong2 tmp[8];
            if (c + 1 < NCHUNK) {
                const ulonglong2 *src = hp2 + (c + 1) * (CH * 128);
#pragma unroll
                for (int q = 0; q < 8; ++q)
                    tmp[q] = src[(st_kk + 4 * q) * 128 + st_pr];
            }

            const ULL *__restrict__ sc = s_half + (c & 1) * (CH * 64) + b0l;
            const float *__restrict__ wf = wsm_f + (c * CH) * 64 + u_local * 4;
#pragma unroll
            for (int kk = 0; kk < CH; ++kk) {
                // weights: (i,f) and (g,o) k-pairs, conflict-free
                ulonglong2 wp0 = *(const ulonglong2 *)(wf + kk * 64);
                ulonglong2 wp1 = *(const ulonglong2 *)(wf + kk * 64 + 32);
                // h: 4 owned batches' k-pairs, conflict-free w/ broadcast
                ulonglong2 h01 = *(const ulonglong2 *)(sc + kk * 64);
                ulonglong2 h23 = *(const ulonglong2 *)(sc + kk * 64 + 2);
                fma2(a00, h01.x, wp0.x); fma2(a01, h01.x, wp0.y);
                fma2(a02, h01.x, wp1.x); fma2(a03, h01.x, wp1.y);
                fma2(a10, h01.y, wp0.x); fma2(a11, h01.y, wp0.y);
                fma2(a12, h01.y, wp1.x); fma2(a13, h01.y, wp1.y);
                fma2(a20, h23.x, wp0.x); fma2(a21, h23.x, wp0.y);
                fma2(a22, h23.x, wp1.x); fma2(a23, h23.x, wp1.y);
                fma2(a30, h23.y, wp0.x); fma2(a31, h23.y, wp0.y);
                fma2(a32, h23.y, wp1.x); fma2(a33, h23.y, wp1.y);
            }

            if (c + 1 < NCHUNK) {
                ulonglong2 *dst = (ulonglong2 *)(s_half + ((c + 1) & 1) * (CH * 64));
#pragma unroll
                for (int q = 0; q < 8; ++q)
                    dst[ht + 128 * q] = tmp[q];
            }
            NBAR(NB_ID);
        }

        // ---- LSTM cell update (gates ordered i,f,g,o), 4 batches ----------
        const int p1 = p ^ 1;
        float *ghn = (float *)(g_hbuf + p1 * (KK * BATCH));
        float hv0, hv1, hv2, hv3;
        {
            float gi = lo2(a00) + hi2(a00) + x0 * wi0 + bs0;
            float gf = lo2(a01) + hi2(a01) + x0 * wi1 + bs1;
            float gg = lo2(a02) + hi2(a02) + x0 * wi2 + bs2;
            float go = lo2(a03) + hi2(a03) + x0 * wi3 + bs3;
            cst0 = sigf(gf) * cst0 + sigf(gi) * tanhf(gg);
            hv0  = sigf(go) * tanhf(cst0);
        }
        {
            float gi = lo2(a10) + hi2(a10) + x1 * wi0 + bs0;
            float gf = lo2(a11) + hi2(a11) + x1 * wi1 + bs1;
            float gg = lo2(a12) + hi2(a12) + x1 * wi2 + bs2;
            float go = lo2(a13) + hi2(a13) + x1 * wi3 + bs3;
            cst1 = sigf(gf) * cst1 + sigf(gi) * tanhf(gg);
            hv1  = sigf(go) * tanhf(cst1);
        }
        {
            float gi = lo2(a20) + hi2(a20) + x2 * wi0 + bs0;
            float gf = lo2(a21) + hi2(a21) + x2 * wi1 + bs1;
            float gg = lo2(a22) + hi2(a22) + x2 * wi2 + bs2;
            float go = lo2(a23) + hi2(a23) + x2 * wi3 + bs3;
            cst2 = sigf(gf) * cst2 + sigf(gi) * tanhf(gg);
            hv2  = sigf(go) * tanhf(cst2);
        }
        {
            float gi = lo2(a30) + hi2(a30) + x3 * wi0 + bs0;
            float gf = lo2(a31) + hi2(a31) + x3 * wi1 + bs1;
            float gg = lo2(a32) + hi2(a32) + x3 * wi2 + bs2;
            float go = lo2(a33) + hi2(a33) + x3 * wi3 + bs3;
            cst3 = sigf(gf) * cst3 + sigf(gi) * tanhf(gg);
            hv3  = sigf(go) * tanhf(cst3);
        }

        ghn[(kk_h * BATCH + bg0 + 0) * 2 + hsub] = hv0;
        ghn[(kk_h * BATCH + bg0 + 1) * 2 + hsub] = hv1;
        ghn[(kk_h * BATCH + bg0 + 2) * 2 + hsub] = hv2;
        ghn[(kk_h * BATCH + bg0 + 3) * 2 + hsub] = hv3;

        // decode partials from registers (no h re-read)
        *(float4 *)&part_s[half][u_local][b0l] =
            make_float4(hv0 * wd, hv1 * wd, hv2 * wd, hv3 * wd);
        NBAR(NB_ID);
        if (ht < 64) {
            float s = part_s[half][0][ht];
#pragma unroll
            for (int q = 1; q < UTILE; ++q) s += part_s[half][q][ht];
            atomicAdd(&out[(bt * BTILE + ht) * TOTT + t], s);   // REDG
        }

        // half-scoped inter-CTA barrier: the other half keeps computing
        ++epoch;
        NBAR(NB_ID);
        if (ht == 0) barrier_core(grp, epoch);
        NBAR(NB_ID);
        p = p1;
    }
}

// ---------------- launch -----------------------------------------------------
extern "C" void kernel_launch(void *const *d_in, const int *in_sizes, int n_in,
                              void *d_out, int out_size) {
    const float *xin  = (const float *)d_in[0];   // input_seq [256,512,1]
    // d_in[1] = future_n (fixed 64, hardcoded)
    const float *Wih  = (const float *)d_in[2];   // [2048,1]
    const float *Whh  = (const float *)d_in[3];   // [2048,512]
    const float *bih  = (const float *)d_in[4];   // [2048]
    const float *bhh  = (const float *)d_in[5];   // [2048]
    const float *Wdec = (const float *)d_in[6];   // [1,512]
    const float *bdec = (const float *)d_in[7];   // [1]
    float *out = (float *)d_out;                  // [256,576,1]

    // 64 KB weights + 64 KB h staging (2 halves x 2 x 16 KB) = 128 KB
    const int SMEM = UTILE * 4 * HID * 4 + 2 * 2 * CH * BTILE * 8;
    static_assert(UTILE * 4 * HID * 4 == 65536, "smem size");
    cudaFuncSetAttribute(lstm_persist_kernel,
                         cudaFuncAttributeMaxDynamicSharedMemorySize, SMEM);

    lstm_persist_kernel<<<NCTA, NTHR, SMEM>>>(xin, Wih, Whh, bih, bhh,
                                              Wdec, bdec, out);
    (void)in_sizes; (void)n_in; (void)out_size;
}